// round 2
// baseline (speedup 1.0000x reference)
#include <cuda_runtime.h>
#include <math.h>

#define Bsz 4
#define Hh 64
#define Ww 64
#define Cc 128
#define NHh 4
#define Kk 7
#define HDd 32
#define Ntok (Bsz*Hh*Ww)
#define MLPD 512

// ---------------- scratch (no allocations allowed) ----------------
__device__ float g_qn [Ntok*Cc];
__device__ float g_kvn[Ntok*Cc];
__device__ float g_q  [Ntok*Cc];
__device__ float g_kv [Ntok*2*Cc];
__device__ float g_att[Ntok*Cc];
__device__ float g_x  [Ntok*Cc];
__device__ float g_xn [Ntok*Cc];
__device__ float g_mid[Ntok*MLPD];

// ---------------- LayerNorm: one warp per token (C=128 = 32 lanes x float4) ----
__global__ void __launch_bounds__(256) ln_kernel(const float* __restrict__ in,
                                                 const float* __restrict__ g,
                                                 const float* __restrict__ b,
                                                 float* __restrict__ out)
{
    int token = blockIdx.x * 8 + (threadIdx.x >> 5);
    int lane  = threadIdx.x & 31;
    const float4 v = ((const float4*)(in + (long)token * Cc))[lane];
    float s = v.x + v.y + v.z + v.w;
    #pragma unroll
    for (int o = 16; o; o >>= 1) s += __shfl_xor_sync(0xffffffffu, s, o);
    float mean = s * (1.0f / Cc);
    float dx = v.x - mean, dy = v.y - mean, dz = v.z - mean, dw = v.w - mean;
    float ss = dx*dx + dy*dy + dz*dz + dw*dw;
    #pragma unroll
    for (int o = 16; o; o >>= 1) ss += __shfl_xor_sync(0xffffffffu, ss, o);
    float inv = rsqrtf(ss * (1.0f / Cc) + 1e-5f);
    float4 gg = ((const float4*)g)[lane];
    float4 bb = ((const float4*)b)[lane];
    float4 o4;
    o4.x = dx * inv * gg.x + bb.x;
    o4.y = dy * inv * gg.y + bb.y;
    o4.z = dz * inv * gg.z + bb.z;
    o4.w = dw * inv * gg.w + bb.w;
    ((float4*)(out + (long)token * Cc))[lane] = o4;
}

// ---------------- SGEMM: 128x128x16 tile, 256 threads, 8x8 per thread -------
// EPI: 0 = +bias; 1 = (+bias)*scale; 2 = +bias +residual; 3 = gelu(+bias)
template<int EPI>
__global__ void __launch_bounds__(256) gemm_kernel(const float* __restrict__ A,
                                                   const float* __restrict__ B,
                                                   const float* __restrict__ bias,
                                                   const float* __restrict__ res,
                                                   float* __restrict__ C,
                                                   int M, int N, int K, float scale)
{
    __shared__ float As[16][132];
    __shared__ float Bs[16][128];
    const int tid = threadIdx.x;
    const int bm = blockIdx.y * 128;
    const int bn = blockIdx.x * 128;
    const int tx = tid & 15, ty = tid >> 4;

    float acc[8][8];
    #pragma unroll
    for (int i = 0; i < 8; i++)
        #pragma unroll
        for (int j = 0; j < 8; j++) acc[i][j] = 0.f;

    for (int k0 = 0; k0 < K; k0 += 16) {
        #pragma unroll
        for (int i = 0; i < 2; i++) {
            int f = tid + i * 256;            // 512 float4 of A tile
            int m = f >> 2, kq = (f & 3) * 4;
            float4 v = *(const float4*)&A[(long)(bm + m) * K + k0 + kq];
            As[kq    ][m] = v.x;
            As[kq + 1][m] = v.y;
            As[kq + 2][m] = v.z;
            As[kq + 3][m] = v.w;
        }
        #pragma unroll
        for (int i = 0; i < 2; i++) {
            int f = tid + i * 256;            // 512 float4 of B tile
            int kk = f >> 5, n4 = (f & 31) * 4;
            *(float4*)&Bs[kk][n4] = *(const float4*)&B[(long)(k0 + kk) * N + bn + n4];
        }
        __syncthreads();
        #pragma unroll
        for (int k = 0; k < 16; k++) {
            float a[8], bb[8];
            *(float4*)&a[0]  = *(float4*)&As[k][ty * 8];
            *(float4*)&a[4]  = *(float4*)&As[k][ty * 8 + 4];
            *(float4*)&bb[0] = *(float4*)&Bs[k][tx * 8];
            *(float4*)&bb[4] = *(float4*)&Bs[k][tx * 8 + 4];
            #pragma unroll
            for (int i = 0; i < 8; i++)
                #pragma unroll
                for (int j = 0; j < 8; j++) acc[i][j] += a[i] * bb[j];
        }
        __syncthreads();
    }

    #pragma unroll
    for (int i = 0; i < 8; i++) {
        long m = bm + ty * 8 + i;
        float cv[8];
        #pragma unroll
        for (int j = 0; j < 8; j++) {
            int n = bn + tx * 8 + j;
            float c = acc[i][j] + bias[n];
            if (EPI == 1) c *= scale;
            if (EPI == 2) c += res[m * N + n];
            if (EPI == 3) c = 0.5f * c * (1.0f + erff(c * 0.70710678118654752f));
            cv[j] = c;
        }
        *(float4*)&C[m * N + bn + tx * 8]     = *(float4*)&cv[0];
        *(float4*)&C[m * N + bn + tx * 8 + 4] = *(float4*)&cv[4];
    }
}

// ---------------- Neighborhood attention ------------------------------------
// Block = (8x8 pixel tile, 2 heads). 128 threads: thread = (pixel, head).
// K/V neighborhood union (14x14 rows x 32 dims x 2 heads) staged in smem with
// stride 36 (16B-aligned float4, de-conflicted banks).
#define TS 8
#define NROWS 14
#define NIDX (NROWS*NROWS)   // 196
#define STRD 36
#define NATT_SMEM (2*2*NIDX*STRD*4)   // 112896 bytes

__global__ void __launch_bounds__(128) natt_kernel(const float* __restrict__ rpb)
{
    extern __shared__ float sm[];
    float* sK = sm;
    float* sV = sm + 2 * NIDX * STRD;

    const int tid = threadIdx.x;
    const int tj = blockIdx.x, ti = blockIdx.y;
    const int b  = blockIdx.z >> 1;
    const int h0 = (blockIdx.z & 1) * 2;
    const int i0 = ti * TS, j0 = tj * TS;
    const int base_i = min(max(i0 - 3, 0), Hh - Kk);
    const int base_j = min(max(j0 - 3, 0), Ww - Kk);

    // stage K,V for 2 heads: 196 rows x 32 float4 each (k-pair then v-pair)
    for (int e = tid; e < NIDX * 32; e += 128) {
        int row = e >> 5, c4 = e & 31;
        int gi = min(base_i + row / NROWS, Hh - 1);
        int gj = min(base_j + row % NROWS, Ww - 1);
        const float4* src = (const float4*)(g_kv + (((long)(b * Hh + gi) * Ww) + gj) * 256);
        int c = c4 * 4;
        if (c < 64) {                       // k, heads h0..h0+1
            float4 v = src[(h0 * 32 + c) >> 2];
            int hl = c >> 5, d = c & 31;
            *(float4*)&sK[(hl * NIDX + row) * STRD + d] = v;
        } else {                            // v
            int cc = c - 64;
            float4 v = src[(128 + h0 * 32 + cc) >> 2];
            int hl = cc >> 5, d = cc & 31;
            *(float4*)&sV[(hl * NIDX + row) * STRD + d] = v;
        }
    }
    __syncthreads();

    const int px = tid & 63, hl = tid >> 6;
    const int h = h0 + hl;
    const int i = i0 + (px >> 3), j = j0 + (px & 7);
    const int si = min(max(i - 3, 0), Hh - Kk);
    const int sj = min(max(j - 3, 0), Ww - Kk);
    const int li = si - base_i, lj = sj - base_j;
    const long np = (long)(b * Hh + i) * Ww + j;

    float4 q[8];
    const float4* qp = (const float4*)(g_q + np * Cc + h * HDd);
    #pragma unroll
    for (int u = 0; u < 8; u++) q[u] = qp[u];

    const float* rp = rpb + h * 169 + (si - i + 6) * 13 + (sj - j + 6);
    const float* kbase = sK + hl * NIDX * STRD;
    const float* vbase = sV + hl * NIDX * STRD;

    float sc[49];
    #pragma unroll
    for (int a = 0; a < 7; a++) {
        #pragma unroll
        for (int bb = 0; bb < 7; bb++) {
            const float4* kk = (const float4*)(kbase + ((li + a) * NROWS + lj + bb) * STRD);
            float s = 0.f;
            #pragma unroll
            for (int u = 0; u < 8; u++) {
                float4 kv4 = kk[u];
                s += q[u].x * kv4.x; s += q[u].y * kv4.y;
                s += q[u].z * kv4.z; s += q[u].w * kv4.w;
            }
            sc[a * 7 + bb] = s + __ldg(&rp[a * 13 + bb]);
        }
    }

    float mx = sc[0];
    #pragma unroll
    for (int n = 1; n < 49; n++) mx = fmaxf(mx, sc[n]);
    float sum = 0.f;
    #pragma unroll
    for (int n = 0; n < 49; n++) { sc[n] = expf(sc[n] - mx); sum += sc[n]; }
    const float inv = 1.0f / sum;

    float4 acc[8];
    #pragma unroll
    for (int u = 0; u < 8; u++) acc[u] = make_float4(0.f, 0.f, 0.f, 0.f);
    #pragma unroll
    for (int a = 0; a < 7; a++) {
        #pragma unroll
        for (int bb = 0; bb < 7; bb++) {
            float p = sc[a * 7 + bb] * inv;
            const float4* vv = (const float4*)(vbase + ((li + a) * NROWS + lj + bb) * STRD);
            #pragma unroll
            for (int u = 0; u < 8; u++) {
                float4 v4 = vv[u];
                acc[u].x += p * v4.x; acc[u].y += p * v4.y;
                acc[u].z += p * v4.z; acc[u].w += p * v4.w;
            }
        }
    }
    float4* op = (float4*)(g_att + np * Cc + h * HDd);
    #pragma unroll
    for (int u = 0; u < 8; u++) op[u] = acc[u];
}

// ---------------- launch -----------------------------------------------------
extern "C" void kernel_launch(void* const* d_in, const int* in_sizes, int n_in,
                              void* d_out, int out_size)
{
    const float* query     = (const float*)d_in[0];
    const float* key_value = (const float*)d_in[1];
    const float* g1 = (const float*)d_in[2],  *b1 = (const float*)d_in[3];
    const float* g2 = (const float*)d_in[4],  *b2 = (const float*)d_in[5];
    const float* g3 = (const float*)d_in[6],  *b3 = (const float*)d_in[7];
    const float* Wq = (const float*)d_in[8],  *bq = (const float*)d_in[9];
    const float* Wkv= (const float*)d_in[10], *bkv= (const float*)d_in[11];
    const float* Wp = (const float*)d_in[12], *bp = (const float*)d_in[13];
    const float* rpb= (const float*)d_in[14];
    const float* W1 = (const float*)d_in[15], *bm1= (const float*)d_in[16];
    const float* W2 = (const float*)d_in[17], *bm2= (const float*)d_in[18];
    float* out = (float*)d_out;

    float *qn, *kvn, *q, *kv, *att, *x, *xn, *mid;
    cudaGetSymbolAddress((void**)&qn,  g_qn);
    cudaGetSymbolAddress((void**)&kvn, g_kvn);
    cudaGetSymbolAddress((void**)&q,   g_q);
    cudaGetSymbolAddress((void**)&kv,  g_kv);
    cudaGetSymbolAddress((void**)&att, g_att);
    cudaGetSymbolAddress((void**)&x,   g_x);
    cudaGetSymbolAddress((void**)&xn,  g_xn);
    cudaGetSymbolAddress((void**)&mid, g_mid);

    cudaFuncSetAttribute(natt_kernel, cudaFuncAttributeMaxDynamicSharedMemorySize, NATT_SMEM);

    // 1-2: LayerNorms of query / key_value
    ln_kernel<<<Ntok / 8, 256>>>(query,     g1, b1, qn);
    ln_kernel<<<Ntok / 8, 256>>>(key_value, g2, b2, kvn);

    // 3: q = (qn @ Wq + bq) * HD^-0.5    [N,128]
    gemm_kernel<1><<<dim3(1, Ntok / 128), 256>>>(qn, Wq, bq, nullptr, q,
                                                 Ntok, 128, 128, 0.17677669529663689f);
    // 4: kv = kvn @ Wkv + bkv            [N,256]
    gemm_kernel<0><<<dim3(2, Ntok / 128), 256>>>(kvn, Wkv, bkv, nullptr, kv,
                                                 Ntok, 256, 128, 1.f);
    // 5: neighborhood attention -> g_att [N,128]
    natt_kernel<<<dim3(Ww / TS, Hh / TS, Bsz * 2), 128, NATT_SMEM>>>(rpb);

    // 6: x = key_value + att @ Wp + bp
    gemm_kernel<2><<<dim3(1, Ntok / 128), 256>>>(att, Wp, bp, key_value, x,
                                                 Ntok, 128, 128, 1.f);
    // 7: xn = LN(x)
    ln_kernel<<<Ntok / 8, 256>>>(x, g3, b3, xn);

    // 8: mid = gelu(xn @ W1 + bm1)       [N,512]
    gemm_kernel<3><<<dim3(4, Ntok / 128), 256>>>(xn, W1, bm1, nullptr, mid,
                                                 Ntok, MLPD, 128, 1.f);
    // 9: out = x + mid @ W2 + bm2        [N,128]
    gemm_kernel<2><<<dim3(1, Ntok / 128), 256>>>(mid, W2, bm2, x, out,
                                                 Ntok, 128, MLPD, 1.f);
}

// round 13
// speedup vs baseline: 2.0014x; 2.0014x over previous
#include <cuda_runtime.h>
#include <cuda_bf16.h>
#include <math.h>
#include <cstdint>

#define Bsz 4
#define Hh 64
#define Ww 64
#define Cc 128
#define NHh 4
#define Kk 7
#define HDd 32
#define Ntok (Bsz*Hh*Ww)
#define MLPD 512
#define QKVN 384

// ---------------- scratch (no allocations allowed) ----------------
__device__ __nv_bfloat16 g_qn [Ntok*Cc];
__device__ __nv_bfloat16 g_kvn[Ntok*Cc];
__device__ float         g_qkv[Ntok*QKVN];   // [q(128) | k(128) | v(128)]
__device__ __nv_bfloat16 g_att[Ntok*Cc];
__device__ float         g_x  [Ntok*Cc];
__device__ __nv_bfloat16 g_xn [Ntok*Cc];
__device__ __nv_bfloat16 g_mid[Ntok*MLPD];
// packed bf16 weights, transposed to [N,K]
__device__ __nv_bfloat16 g_wqkv[QKVN*Cc];
__device__ __nv_bfloat16 g_wp  [Cc*Cc];
__device__ __nv_bfloat16 g_w1  [MLPD*Cc];
__device__ __nv_bfloat16 g_w2  [Cc*MLPD];
__device__ float         g_bqkv[QKVN];

// ---------------- helpers ------------------------------------
__device__ __forceinline__ uint32_t smem_u32(const void* p) {
    uint32_t a;
    asm("{ .reg .u64 t; cvta.to.shared.u64 t, %1; cvt.u32.u64 %0, t; }" : "=r"(a) : "l"(p));
    return a;
}
__device__ __forceinline__ void cp16(uint32_t dst, const void* src) {
    asm volatile("cp.async.cg.shared.global [%0], [%1], 16;" :: "r"(dst), "l"(src));
}
__device__ __forceinline__ void cp_commit() {
    asm volatile("cp.async.commit_group;" ::: "memory");
}
__device__ __forceinline__ void cp_wait0() {
    asm volatile("cp.async.wait_group 0;" ::: "memory");
}
__device__ __forceinline__ void ldmx4(uint32_t* r, uint32_t addr) {
    asm volatile("ldmatrix.sync.aligned.m8n8.x4.shared.b16 {%0,%1,%2,%3}, [%4];"
                 : "=r"(r[0]), "=r"(r[1]), "=r"(r[2]), "=r"(r[3]) : "r"(addr));
}
__device__ __forceinline__ void mma16816(float* d, const uint32_t* a,
                                         uint32_t b0, uint32_t b1) {
    asm volatile(
        "mma.sync.aligned.m16n8k16.row.col.f32.bf16.bf16.f32 "
        "{%0,%1,%2,%3},{%4,%5,%6,%7},{%8,%9},{%0,%1,%2,%3};"
        : "+f"(d[0]), "+f"(d[1]), "+f"(d[2]), "+f"(d[3])
        : "r"(a[0]), "r"(a[1]), "r"(a[2]), "r"(a[3]), "r"(b0), "r"(b1));
}

// ---------------- weight pack: W[K,N] f32 -> out[N,K] bf16 (*scale) --------
__global__ void pack_w(const float* __restrict__ W, __nv_bfloat16* __restrict__ out,
                       int K, int N, float scale)
{
    int idx = blockIdx.x * 256 + threadIdx.x;
    if (idx >= N * K) return;
    int n = idx / K, k = idx - n * K;
    out[idx] = __float2bfloat16(W[(long)k * N + n] * scale);
}
__global__ void pack_bias_qkv(const float* __restrict__ bq, const float* __restrict__ bkv,
                              float* __restrict__ out)
{
    int n = blockIdx.x * 128 + threadIdx.x;
    out[n] = (n < 128) ? bq[n] * 0.17677669529663689f : bkv[n - 128];
}

// ---------------- LayerNorm: one warp per token, bf16 out -------------------
__global__ void __launch_bounds__(256) ln_kernel(const float* __restrict__ in,
                                                 const float* __restrict__ g,
                                                 const float* __restrict__ b,
                                                 __nv_bfloat16* __restrict__ out)
{
    int token = blockIdx.x * 8 + (threadIdx.x >> 5);
    int lane  = threadIdx.x & 31;
    const float4 v = ((const float4*)(in + (long)token * Cc))[lane];
    float s = v.x + v.y + v.z + v.w;
    #pragma unroll
    for (int o = 16; o; o >>= 1) s += __shfl_xor_sync(0xffffffffu, s, o);
    float mean = s * (1.0f / Cc);
    float dx = v.x - mean, dy = v.y - mean, dz = v.z - mean, dw = v.w - mean;
    float ss = dx*dx + dy*dy + dz*dz + dw*dw;
    #pragma unroll
    for (int o = 16; o; o >>= 1) ss += __shfl_xor_sync(0xffffffffu, ss, o);
    float inv = rsqrtf(ss * (1.0f / Cc) + 1e-5f);
    float4 gg = ((const float4*)g)[lane];
    float4 bb = ((const float4*)b)[lane];
    __nv_bfloat162* op = (__nv_bfloat162*)(out + (long)token * Cc);
    op[lane*2]   = __floats2bfloat162_rn(dx*inv*gg.x + bb.x, dy*inv*gg.y + bb.y);
    op[lane*2+1] = __floats2bfloat162_rn(dz*inv*gg.z + bb.z, dw*inv*gg.w + bb.w);
}

// ---------------- bf16 mma.sync GEMM: C[M,:] = A[M,K] @ B[N,K]^T -------------
// Block tile 128x128, 8 warps (4 M x 2 N), warp tile 32x64, K-chunk 32,
// double-buffered cp.async, ldmatrix fragments, padded smem (stride 40 bf16).
// EPI: 0 = +bias -> f32; 1 = +bias +res -> f32; 2 = gelu(+bias) -> bf16
#define SSTR 40
#define STILE (128*SSTR)   // elements per tile per buffer

template<int EPI>
__global__ void __launch_bounds__(256) gemm_mma(const __nv_bfloat16* __restrict__ A,
                                                const __nv_bfloat16* __restrict__ Bw,
                                                const float* __restrict__ bias,
                                                const float* __restrict__ res,
                                                void* __restrict__ Cout,
                                                int M, int K, int ldc)
{
    __shared__ __nv_bfloat16 As[2][STILE];
    __shared__ __nv_bfloat16 Bs[2][STILE];

    const int tid  = threadIdx.x;
    const int lane = tid & 31;
    const int wid  = tid >> 5;
    const int wm   = wid >> 1;        // 0..3
    const int wn   = wid & 1;         // 0..1
    const int bm   = blockIdx.y * 128;
    const int bn   = blockIdx.x * 128;

    const uint32_t sA = smem_u32(&As[0][0]);
    const uint32_t sB = smem_u32(&Bs[0][0]);

    // global load coords: 512 x 16B per tile, 2 per thread
    const int r0  = tid >> 2,  kc0 = (tid & 3);
    const int r1  = (tid + 256) >> 2, kc1 = ((tid + 256) & 3);

    // ldmatrix element offsets (within one buffer)
    uint32_t aoff[2], boff[4];
    #pragma unroll
    for (int mt = 0; mt < 2; mt++)
        aoff[mt] = (uint32_t)((wm*32 + mt*16 + (lane & 15)) * SSTR + (lane >> 4) * 8);
    #pragma unroll
    for (int ng = 0; ng < 4; ng++)
        boff[ng] = (uint32_t)((wn*64 + ng*16 + (lane & 7) + ((lane >> 3) & 1) * 8) * SSTR
                              + ((lane >> 4) & 1) * 8);

    float acc[2][8][4];
    #pragma unroll
    for (int i = 0; i < 2; i++)
        #pragma unroll
        for (int j = 0; j < 8; j++)
            #pragma unroll
            for (int t = 0; t < 4; t++) acc[i][j][t] = 0.f;

    const int chunks = K >> 5;

    // prologue: load chunk 0 into buffer 0
    {
        cp16(sA + (uint32_t)(r0 * SSTR + kc0 * 8) * 2, A  + (long)(bm + r0) * K + kc0 * 8);
        cp16(sA + (uint32_t)(r1 * SSTR + kc1 * 8) * 2, A  + (long)(bm + r1) * K + kc1 * 8);
        cp16(sB + (uint32_t)(r0 * SSTR + kc0 * 8) * 2, Bw + (long)(bn + r0) * K + kc0 * 8);
        cp16(sB + (uint32_t)(r1 * SSTR + kc1 * 8) * 2, Bw + (long)(bn + r1) * K + kc1 * 8);
        cp_commit();
    }

    for (int c = 0; c < chunks; c++) {
        const int buf = c & 1;
        cp_wait0();
        __syncthreads();
        if (c + 1 < chunks) {
            const int nb = (c + 1) & 1;
            const int k0 = (c + 1) << 5;
            const uint32_t da = sA + (uint32_t)nb * STILE * 2;
            const uint32_t db = sB + (uint32_t)nb * STILE * 2;
            cp16(da + (uint32_t)(r0 * SSTR + kc0 * 8) * 2, A  + (long)(bm + r0) * K + k0 + kc0 * 8);
            cp16(da + (uint32_t)(r1 * SSTR + kc1 * 8) * 2, A  + (long)(bm + r1) * K + k0 + kc1 * 8);
            cp16(db + (uint32_t)(r0 * SSTR + kc0 * 8) * 2, Bw + (long)(bn + r0) * K + k0 + kc0 * 8);
            cp16(db + (uint32_t)(r1 * SSTR + kc1 * 8) * 2, Bw + (long)(bn + r1) * K + k0 + kc1 * 8);
            cp_commit();
        }
        const uint32_t ba = sA + (uint32_t)buf * STILE * 2;
        const uint32_t bb = sB + (uint32_t)buf * STILE * 2;
        #pragma unroll
        for (int ks = 0; ks < 2; ks++) {
            uint32_t af[2][4], bf[4][4];
            #pragma unroll
            for (int mt = 0; mt < 2; mt++)
                ldmx4(af[mt], ba + (aoff[mt] + ks * 16) * 2);
            #pragma unroll
            for (int ng = 0; ng < 4; ng++)
                ldmx4(bf[ng], bb + (boff[ng] + ks * 16) * 2);
            #pragma unroll
            for (int mt = 0; mt < 2; mt++)
                #pragma unroll
                for (int nt = 0; nt < 8; nt++) {
                    const int ng = nt >> 1, sel = nt & 1;
                    mma16816(acc[mt][nt], af[mt], bf[ng][sel], bf[ng][sel + 2]);
                }
        }
    }

    // ---------------- epilogue ----------------
    const int rowb = bm + wm * 32 + (lane >> 2);
    const int nloc0 = wn * 64 + (lane & 3) * 2;   // local n (bias/res/C col within launch)
    #pragma unroll
    for (int mt = 0; mt < 2; mt++) {
        #pragma unroll
        for (int nt = 0; nt < 8; nt++) {
            const int nl = bn + nloc0 + nt * 8;
            const float b0 = bias[nl], b1 = bias[nl + 1];
            const long m0 = rowb + mt * 16;
            const long m1 = m0 + 8;
            float v00 = acc[mt][nt][0] + b0, v01 = acc[mt][nt][1] + b1;
            float v10 = acc[mt][nt][2] + b0, v11 = acc[mt][nt][3] + b1;
            if (EPI == 1) {
                float2 rv0 = *(const float2*)(res + m0 * ldc + nl);
                float2 rv1 = *(const float2*)(res + m1 * ldc + nl);
                v00 += rv0.x; v01 += rv0.y; v10 += rv1.x; v11 += rv1.y;
            }
            if (EPI == 2) {
                v00 = 0.5f * v00 * (1.0f + erff(v00 * 0.70710678118654752f));
                v01 = 0.5f * v01 * (1.0f + erff(v01 * 0.70710678118654752f));
                v10 = 0.5f * v10 * (1.0f + erff(v10 * 0.70710678118654752f));
                v11 = 0.5f * v11 * (1.0f + erff(v11 * 0.70710678118654752f));
                __nv_bfloat16* O = (__nv_bfloat16*)Cout;
                *(__nv_bfloat162*)(O + m0 * ldc + nl) = __floats2bfloat162_rn(v00, v01);
                *(__nv_bfloat162*)(O + m1 * ldc + nl) = __floats2bfloat162_rn(v10, v11);
            } else {
                float* O = (float*)Cout;
                *(float2*)(O + m0 * ldc + nl) = make_float2(v00, v01);
                *(float2*)(O + m1 * ldc + nl) = make_float2(v10, v11);
            }
        }
    }
}

// ---------------- Neighborhood attention ------------------------------------
#define TS 8
#define NROWS 14
#define NIDX (NROWS*NROWS)
#define STRD 36
#define NATT_SMEM (2*2*NIDX*STRD*4)

__global__ void __launch_bounds__(128) natt_kernel(const float* __restrict__ rpb)
{
    extern __shared__ float sm[];
    float* sK = sm;
    float* sV = sm + 2 * NIDX * STRD;

    const int tid = threadIdx.x;
    const int tj = blockIdx.x, ti = blockIdx.y;
    const int b  = blockIdx.z >> 1;
    const int h0 = (blockIdx.z & 1) * 2;
    const int i0 = ti * TS, j0 = tj * TS;
    const int base_i = min(max(i0 - 3, 0), Hh - Kk);
    const int base_j = min(max(j0 - 3, 0), Ww - Kk);

    for (int e = tid; e < NIDX * 32; e += 128) {
        int row = e >> 5, c4 = e & 31;
        int gi = min(base_i + row / NROWS, Hh - 1);
        int gj = min(base_j + row % NROWS, Ww - 1);
        const float4* src = (const float4*)(g_qkv + (((long)(b * Hh + gi) * Ww) + gj) * QKVN);
        int c = c4 * 4;
        if (c < 64) {                       // k (cols 128..255 of qkv)
            float4 v = src[(128 + h0 * 32 + c) >> 2];
            int hl = c >> 5, d = c & 31;
            *(float4*)&sK[(hl * NIDX + row) * STRD + d] = v;
        } else {                            // v (cols 256..383)
            int cc = c - 64;
            float4 v = src[(256 + h0 * 32 + cc) >> 2];
            int hl = cc >> 5, d = cc & 31;
            *(float4*)&sV[(hl * NIDX + row) * STRD + d] = v;
        }
    }
    __syncthreads();

    const int px = tid & 63, hl = tid >> 6;
    const int h = h0 + hl;
    const int i = i0 + (px >> 3), j = j0 + (px & 7);
    const int si = min(max(i - 3, 0), Hh - Kk);
    const int sj = min(max(j - 3, 0), Ww - Kk);
    const int li = si - base_i, lj = sj - base_j;
    const long np = (long)(b * Hh + i) * Ww + j;

    float4 q[8];
    const float4* qp = (const float4*)(g_qkv + np * QKVN + h * HDd);
    #pragma unroll
    for (int u = 0; u < 8; u++) q[u] = qp[u];

    const float* rp = rpb + h * 169 + (si - i + 6) * 13 + (sj - j + 6);
    const float* kbase = sK + hl * NIDX * STRD;
    const float* vbase = sV + hl * NIDX * STRD;

    float sc[49];
    #pragma unroll
    for (int a = 0; a < 7; a++) {
        #pragma unroll
        for (int bb = 0; bb < 7; bb++) {
            const float4* kk = (const float4*)(kbase + ((li + a) * NROWS + lj + bb) * STRD);
            float s = 0.f;
            #pragma unroll
            for (int u = 0; u < 8; u++) {
                float4 kv4 = kk[u];
                s += q[u].x * kv4.x; s += q[u].y * kv4.y;
                s += q[u].z * kv4.z; s += q[u].w * kv4.w;
            }
            sc[a * 7 + bb] = s + __ldg(&rp[a * 13 + bb]);
        }
    }

    float mx = sc[0];
    #pragma unroll
    for (int n = 1; n < 49; n++) mx = fmaxf(mx, sc[n]);
    float sum = 0.f;
    #pragma unroll
    for (int n = 0; n < 49; n++) { sc[n] = expf(sc[n] - mx); sum += sc[n]; }
    const float inv = 1.0f / sum;

    float4 acc[8];
    #pragma unroll
    for (int u = 0; u < 8; u++) acc[u] = make_float4(0.f, 0.f, 0.f, 0.f);
    #pragma unroll
    for (int a = 0; a < 7; a++) {
        #pragma unroll
        for (int bb = 0; bb < 7; bb++) {
            float p = sc[a * 7 + bb] * inv;
            const float4* vv = (const float4*)(vbase + ((li + a) * NROWS + lj + bb) * STRD);
            #pragma unroll
            for (int u = 0; u < 8; u++) {
                float4 v4 = vv[u];
                acc[u].x += p * v4.x; acc[u].y += p * v4.y;
                acc[u].z += p * v4.z; acc[u].w += p * v4.w;
            }
        }
    }
    __nv_bfloat162* op = (__nv_bfloat162*)(g_att + np * Cc + h * HDd);
    #pragma unroll
    for (int u = 0; u < 8; u++) {
        op[u*2]   = __floats2bfloat162_rn(acc[u].x, acc[u].y);
        op[u*2+1] = __floats2bfloat162_rn(acc[u].z, acc[u].w);
    }
}

// ---------------- launch -----------------------------------------------------
extern "C" void kernel_launch(void* const* d_in, const int* in_sizes, int n_in,
                              void* d_out, int out_size)
{
    const float* query     = (const float*)d_in[0];
    const float* key_value = (const float*)d_in[1];
    const float* g1 = (const float*)d_in[2],  *b1 = (const float*)d_in[3];
    const float* g2 = (const float*)d_in[4],  *b2 = (const float*)d_in[5];
    const float* g3 = (const float*)d_in[6],  *b3 = (const float*)d_in[7];
    const float* Wq = (const float*)d_in[8],  *bq = (const float*)d_in[9];
    const float* Wkv= (const float*)d_in[10], *bkv= (const float*)d_in[11];
    const float* Wp = (const float*)d_in[12], *bp = (const float*)d_in[13];
    const float* rpb= (const float*)d_in[14];
    const float* W1 = (const float*)d_in[15], *bm1= (const float*)d_in[16];
    const float* W2 = (const float*)d_in[17], *bm2= (const float*)d_in[18];
    float* out = (float*)d_out;

    __nv_bfloat16 *qn, *kvn, *att, *xn, *mid, *wqkv, *wp, *w1, *w2;
    float *qkv, *x, *bqkv;
    cudaGetSymbolAddress((void**)&qn,   g_qn);
    cudaGetSymbolAddress((void**)&kvn,  g_kvn);
    cudaGetSymbolAddress((void**)&qkv,  g_qkv);
    cudaGetSymbolAddress((void**)&att,  g_att);
    cudaGetSymbolAddress((void**)&x,    g_x);
    cudaGetSymbolAddress((void**)&xn,   g_xn);
    cudaGetSymbolAddress((void**)&mid,  g_mid);
    cudaGetSymbolAddress((void**)&wqkv, g_wqkv);
    cudaGetSymbolAddress((void**)&wp,   g_wp);
    cudaGetSymbolAddress((void**)&w1,   g_w1);
    cudaGetSymbolAddress((void**)&w2,   g_w2);
    cudaGetSymbolAddress((void**)&bqkv, g_bqkv);

    cudaFuncSetAttribute(natt_kernel, cudaFuncAttributeMaxDynamicSharedMemorySize, NATT_SMEM);

    // weight packing (transpose + bf16, q-scale folded)
    pack_w<<<(128*128 + 255)/256, 256>>>(Wq,  wqkv,            128, 128, 0.17677669529663689f);
    pack_w<<<(256*128 + 255)/256, 256>>>(Wkv, wqkv + 128*128,  128, 256, 1.f);
    pack_w<<<(128*128 + 255)/256, 256>>>(Wp,  wp,              128, 128, 1.f);
    pack_w<<<(512*128 + 255)/256, 256>>>(W1,  w1,              128, 512, 1.f);
    pack_w<<<(128*512 + 255)/256, 256>>>(W2,  w2,              512, 128, 1.f);
    pack_bias_qkv<<<3, 128>>>(bq, bkv, bqkv);

    // LayerNorms -> bf16
    ln_kernel<<<Ntok / 8, 256>>>(query,     g1, b1, qn);
    ln_kernel<<<Ntok / 8, 256>>>(key_value, g2, b2, kvn);

    // q = (qn @ Wq + bq)*scale -> qkv cols [0,128)
    gemm_mma<0><<<dim3(1, Ntok/128), 256>>>(qn, wqkv, bqkv, nullptr, qkv,
                                            Ntok, 128, QKVN);
    // kv = kvn @ Wkv + bkv     -> qkv cols [128,384)
    gemm_mma<0><<<dim3(2, Ntok/128), 256>>>(kvn, wqkv + 128*128, bqkv + 128, nullptr,
                                            qkv + 128, Ntok, 128, QKVN);

    // neighborhood attention -> att (bf16)
    natt_kernel<<<dim3(Ww/TS, Hh/TS, Bsz*2), 128, NATT_SMEM>>>(rpb);

    // x = key_value + att @ Wp + bp   (f32)
    gemm_mma<1><<<dim3(1, Ntok/128), 256>>>(att, wp, bp, key_value, x,
                                            Ntok, 128, 128);
    // xn = LN(x) -> bf16
    ln_kernel<<<Ntok / 8, 256>>>(x, g3, b3, xn);

    // mid = gelu(xn @ W1 + bm1) -> bf16
    gemm_mma<2><<<dim3(4, Ntok/128), 256>>>(xn, w1, bm1, nullptr, mid,
                                            Ntok, 128, MLPD);
    // out = x + mid @ W2 + bm2  (f32)
    gemm_mma<1><<<dim3(1, Ntok/128), 256>>>(mid, w2, bm2, x, out,
                                            Ntok, MLPD, 128);
}

// round 15
// speedup vs baseline: 2.1735x; 1.0860x over previous
#include <cuda_runtime.h>
#include <cuda_bf16.h>
#include <math.h>
#include <cstdint>

#define Bsz 4
#define Hh 64
#define Ww 64
#define Cc 128
#define NHh 4
#define Kk 7
#define HDd 32
#define Ntok (Bsz*Hh*Ww)
#define MLPD 512
#define QKVN 384

// ---------------- scratch (no allocations allowed) ----------------
__device__ __nv_bfloat16 g_qn [Ntok*Cc];
__device__ __nv_bfloat16 g_kvn[Ntok*Cc];
__device__ float         g_qkv[Ntok*QKVN];   // [q(128) | k(128) | v(128)]
__device__ __nv_bfloat16 g_att[Ntok*Cc];
__device__ float         g_x  [Ntok*Cc];
__device__ __nv_bfloat16 g_xn [Ntok*Cc];
__device__ __nv_bfloat16 g_mid[Ntok*MLPD];
// packed bf16 weights, transposed to [N,K]
__device__ __nv_bfloat16 g_wqkv[QKVN*Cc];
__device__ __nv_bfloat16 g_wp  [Cc*Cc];
__device__ __nv_bfloat16 g_w1  [MLPD*Cc];
__device__ __nv_bfloat16 g_w2  [Cc*MLPD];
__device__ float         g_bqkv[QKVN];

// ---------------- helpers ------------------------------------
__device__ __forceinline__ uint32_t smem_u32(const void* p) {
    uint32_t a;
    asm("{ .reg .u64 t; cvta.to.shared.u64 t, %1; cvt.u32.u64 %0, t; }" : "=r"(a) : "l"(p));
    return a;
}
__device__ __forceinline__ void cp16(uint32_t dst, const void* src) {
    asm volatile("cp.async.cg.shared.global [%0], [%1], 16;" :: "r"(dst), "l"(src));
}
__device__ __forceinline__ void cp_commit() {
    asm volatile("cp.async.commit_group;" ::: "memory");
}
__device__ __forceinline__ void cp_wait0() {
    asm volatile("cp.async.wait_group 0;" ::: "memory");
}
__device__ __forceinline__ void ldmx4(uint32_t* r, uint32_t addr) {
    asm volatile("ldmatrix.sync.aligned.m8n8.x4.shared.b16 {%0,%1,%2,%3}, [%4];"
                 : "=r"(r[0]), "=r"(r[1]), "=r"(r[2]), "=r"(r[3]) : "r"(addr));
}
__device__ __forceinline__ void mma16816(float* d, const uint32_t* a,
                                         uint32_t b0, uint32_t b1) {
    asm volatile(
        "mma.sync.aligned.m16n8k16.row.col.f32.bf16.bf16.f32 "
        "{%0,%1,%2,%3},{%4,%5,%6,%7},{%8,%9},{%0,%1,%2,%3};"
        : "+f"(d[0]), "+f"(d[1]), "+f"(d[2]), "+f"(d[3])
        : "r"(a[0]), "r"(a[1]), "r"(a[2]), "r"(a[3]), "r"(b0), "r"(b1));
}

// ---------------- fused weight pack: coalesced 32x32 tile transpose ---------
// blocks 0..191: weight tiles; blocks 192..193: biases.
__global__ void __launch_bounds__(256) pack_all(const float* __restrict__ Wq,
                                                const float* __restrict__ Wkv,
                                                const float* __restrict__ Wp,
                                                const float* __restrict__ W1,
                                                const float* __restrict__ W2,
                                                const float* __restrict__ bq,
                                                const float* __restrict__ bkv)
{
    __shared__ float t[32][33];
    const int blk = blockIdx.x;
    if (blk >= 192) {
        int n = threadIdx.x + (blk - 192) * 256;
        if (n < QKVN)
            g_bqkv[n] = (n < 128) ? bq[n] * 0.17677669529663689f : bkv[n - 128];
        return;
    }
    const float* W; __nv_bfloat16* out; int K, N, tile0; float scale = 1.f;
    if (blk < 16)       { W = Wq;  out = g_wqkv;           K = 128; N = 128; tile0 = 0;
                          scale = 0.17677669529663689f; }
    else if (blk < 48)  { W = Wkv; out = g_wqkv + 128*128; K = 128; N = 256; tile0 = 16; }
    else if (blk < 64)  { W = Wp;  out = g_wp;             K = 128; N = 128; tile0 = 48; }
    else if (blk < 128) { W = W1;  out = g_w1;             K = 128; N = 512; tile0 = 64; }
    else                { W = W2;  out = g_w2;             K = 512; N = 128; tile0 = 128; }
    const int t_id = blk - tile0;
    const int ntn  = N >> 5;
    const int tk = t_id / ntn, tn = t_id % ntn;
    const int tx = threadIdx.x & 31, ty = threadIdx.x >> 5;
    #pragma unroll
    for (int r = 0; r < 4; r++) {
        int k = tk * 32 + ty + r * 8;
        t[ty + r * 8][tx] = W[(long)k * N + tn * 32 + tx];
    }
    __syncthreads();
    #pragma unroll
    for (int r = 0; r < 4; r++) {
        int n = tn * 32 + ty + r * 8;
        out[(long)n * K + tk * 32 + tx] = __float2bfloat16(t[tx][ty + r * 8] * scale);
    }
}

// ---------------- LayerNorm: one warp per token, bf16 out, dual-input -------
__global__ void __launch_bounds__(256) ln2_kernel(const float* __restrict__ inA,
                                                  const float* __restrict__ gA,
                                                  const float* __restrict__ bA,
                                                  __nv_bfloat16* __restrict__ outA,
                                                  const float* __restrict__ inB,
                                                  const float* __restrict__ gB,
                                                  const float* __restrict__ bB,
                                                  __nv_bfloat16* __restrict__ outB)
{
    const float* in; const float* g; const float* b; __nv_bfloat16* out;
    if (blockIdx.y == 0) { in = inA; g = gA; b = bA; out = outA; }
    else                 { in = inB; g = gB; b = bB; out = outB; }
    int token = blockIdx.x * 8 + (threadIdx.x >> 5);
    int lane  = threadIdx.x & 31;
    const float4 v = ((const float4*)(in + (long)token * Cc))[lane];
    float s = v.x + v.y + v.z + v.w;
    #pragma unroll
    for (int o = 16; o; o >>= 1) s += __shfl_xor_sync(0xffffffffu, s, o);
    float mean = s * (1.0f / Cc);
    float dx = v.x - mean, dy = v.y - mean, dz = v.z - mean, dw = v.w - mean;
    float ss = dx*dx + dy*dy + dz*dz + dw*dw;
    #pragma unroll
    for (int o = 16; o; o >>= 1) ss += __shfl_xor_sync(0xffffffffu, ss, o);
    float inv = rsqrtf(ss * (1.0f / Cc) + 1e-5f);
    float4 gg = ((const float4*)g)[lane];
    float4 bb = ((const float4*)b)[lane];
    __nv_bfloat162* op = (__nv_bfloat162*)(out + (long)token * Cc);
    op[lane*2]   = __floats2bfloat162_rn(dx*inv*gg.x + bb.x, dy*inv*gg.y + bb.y);
    op[lane*2+1] = __floats2bfloat162_rn(dz*inv*gg.z + bb.z, dw*inv*gg.w + bb.w);
}

// ---------------- bf16 mma.sync GEMM: C[M,:] = A[M,K] @ B[N,K]^T -------------
// Block tile 128x128, 8 warps (4 M x 2 N), warp tile 32x64, K-chunk 32,
// double-buffered cp.async, ldmatrix fragments, padded smem (stride 40 bf16).
// A2: alternate A matrix used by blocks with blockIdx.x > 0 (QKV fusion);
// pass A2 == A for ordinary GEMMs.
// EPI: 0 = +bias -> f32; 1 = +bias +res -> f32; 2 = gelu(+bias) -> bf16
#define SSTR 40
#define STILE (128*SSTR)   // elements per tile per buffer

template<int EPI>
__global__ void __launch_bounds__(256) gemm_mma(const __nv_bfloat16* __restrict__ A,
                                                const __nv_bfloat16* __restrict__ A2,
                                                const __nv_bfloat16* __restrict__ Bw,
                                                const float* __restrict__ bias,
                                                const float* __restrict__ res,
                                                void* __restrict__ Cout,
                                                int M, int K, int ldc)
{
    __shared__ __nv_bfloat16 As[2][STILE];
    __shared__ __nv_bfloat16 Bs[2][STILE];

    const int tid  = threadIdx.x;
    const int lane = tid & 31;
    const int wid  = tid >> 5;
    const int wm   = wid >> 1;        // 0..3
    const int wn   = wid & 1;         // 0..1
    const int bm   = blockIdx.y * 128;
    const int bn   = blockIdx.x * 128;

    const __nv_bfloat16* __restrict__ Ause = (blockIdx.x == 0) ? A : A2;

    const uint32_t sA = smem_u32(&As[0][0]);
    const uint32_t sB = smem_u32(&Bs[0][0]);

    // global load coords: 512 x 16B per tile, 2 per thread
    const int r0  = tid >> 2,  kc0 = (tid & 3);
    const int r1  = (tid + 256) >> 2, kc1 = ((tid + 256) & 3);

    // ldmatrix element offsets (within one buffer)
    uint32_t aoff[2], boff[4];
    #pragma unroll
    for (int mt = 0; mt < 2; mt++)
        aoff[mt] = (uint32_t)((wm*32 + mt*16 + (lane & 15)) * SSTR + (lane >> 4) * 8);
    #pragma unroll
    for (int ng = 0; ng < 4; ng++)
        boff[ng] = (uint32_t)((wn*64 + ng*16 + (lane & 7) + ((lane >> 3) & 1) * 8) * SSTR
                              + ((lane >> 4) & 1) * 8);

    float acc[2][8][4];
    #pragma unroll
    for (int i = 0; i < 2; i++)
        #pragma unroll
        for (int j = 0; j < 8; j++)
            #pragma unroll
            for (int t = 0; t < 4; t++) acc[i][j][t] = 0.f;

    const int chunks = K >> 5;

    // prologue: load chunk 0 into buffer 0
    {
        cp16(sA + (uint32_t)(r0 * SSTR + kc0 * 8) * 2, Ause + (long)(bm + r0) * K + kc0 * 8);
        cp16(sA + (uint32_t)(r1 * SSTR + kc1 * 8) * 2, Ause + (long)(bm + r1) * K + kc1 * 8);
        cp16(sB + (uint32_t)(r0 * SSTR + kc0 * 8) * 2, Bw   + (long)(bn + r0) * K + kc0 * 8);
        cp16(sB + (uint32_t)(r1 * SSTR + kc1 * 8) * 2, Bw   + (long)(bn + r1) * K + kc1 * 8);
        cp_commit();
    }

    for (int c = 0; c < chunks; c++) {
        const int buf = c & 1;
        cp_wait0();
        __syncthreads();
        if (c + 1 < chunks) {
            const int nb = (c + 1) & 1;
            const int k0 = (c + 1) << 5;
            const uint32_t da = sA + (uint32_t)nb * STILE * 2;
            const uint32_t db = sB + (uint32_t)nb * STILE * 2;
            cp16(da + (uint32_t)(r0 * SSTR + kc0 * 8) * 2, Ause + (long)(bm + r0) * K + k0 + kc0 * 8);
            cp16(da + (uint32_t)(r1 * SSTR + kc1 * 8) * 2, Ause + (long)(bm + r1) * K + k0 + kc1 * 8);
            cp16(db + (uint32_t)(r0 * SSTR + kc0 * 8) * 2, Bw   + (long)(bn + r0) * K + k0 + kc0 * 8);
            cp16(db + (uint32_t)(r1 * SSTR + kc1 * 8) * 2, Bw   + (long)(bn + r1) * K + k0 + kc1 * 8);
            cp_commit();
        }
        const uint32_t ba = sA + (uint32_t)buf * STILE * 2;
        const uint32_t bb = sB + (uint32_t)buf * STILE * 2;
        #pragma unroll
        for (int ks = 0; ks < 2; ks++) {
            uint32_t af[2][4], bf[4][4];
            #pragma unroll
            for (int mt = 0; mt < 2; mt++)
                ldmx4(af[mt], ba + (aoff[mt] + ks * 16) * 2);
            #pragma unroll
            for (int ng = 0; ng < 4; ng++)
                ldmx4(bf[ng], bb + (boff[ng] + ks * 16) * 2);
            #pragma unroll
            for (int mt = 0; mt < 2; mt++)
                #pragma unroll
                for (int nt = 0; nt < 8; nt++) {
                    const int ng = nt >> 1, sel = nt & 1;
                    mma16816(acc[mt][nt], af[mt], bf[ng][sel], bf[ng][sel + 2]);
                }
        }
    }

    // ---------------- epilogue ----------------
    const int rowb = bm + wm * 32 + (lane >> 2);
    const int nloc0 = wn * 64 + (lane & 3) * 2;
    #pragma unroll
    for (int mt = 0; mt < 2; mt++) {
        #pragma unroll
        for (int nt = 0; nt < 8; nt++) {
            const int nl = bn + nloc0 + nt * 8;
            const float b0 = bias[nl], b1 = bias[nl + 1];
            const long m0 = rowb + mt * 16;
            const long m1 = m0 + 8;
            float v00 = acc[mt][nt][0] + b0, v01 = acc[mt][nt][1] + b1;
            float v10 = acc[mt][nt][2] + b0, v11 = acc[mt][nt][3] + b1;
            if (EPI == 1) {
                float2 rv0 = *(const float2*)(res + m0 * ldc + nl);
                float2 rv1 = *(const float2*)(res + m1 * ldc + nl);
                v00 += rv0.x; v01 += rv0.y; v10 += rv1.x; v11 += rv1.y;
            }
            if (EPI == 2) {
                v00 = 0.5f * v00 * (1.0f + erff(v00 * 0.70710678118654752f));
                v01 = 0.5f * v01 * (1.0f + erff(v01 * 0.70710678118654752f));
                v10 = 0.5f * v10 * (1.0f + erff(v10 * 0.70710678118654752f));
                v11 = 0.5f * v11 * (1.0f + erff(v11 * 0.70710678118654752f));
                __nv_bfloat16* O = (__nv_bfloat16*)Cout;
                *(__nv_bfloat162*)(O + m0 * ldc + nl) = __floats2bfloat162_rn(v00, v01);
                *(__nv_bfloat162*)(O + m1 * ldc + nl) = __floats2bfloat162_rn(v10, v11);
            } else {
                float* O = (float*)Cout;
                *(float2*)(O + m0 * ldc + nl) = make_float2(v00, v01);
                *(float2*)(O + m1 * ldc + nl) = make_float2(v10, v11);
            }
        }
    }
}

// ---------------- Neighborhood attention ------------------------------------
#define TS 8
#define NROWS 14
#define NIDX (NROWS*NROWS)
#define STRD 36
#define NATT_SMEM (2*2*NIDX*STRD*4)

__global__ void __launch_bounds__(128) natt_kernel(const float* __restrict__ rpb)
{
    extern __shared__ float sm[];
    float* sK = sm;
    float* sV = sm + 2 * NIDX * STRD;

    const int tid = threadIdx.x;
    const int tj = blockIdx.x, ti = blockIdx.y;
    const int b  = blockIdx.z >> 1;
    const int h0 = (blockIdx.z & 1) * 2;
    const int i0 = ti * TS, j0 = tj * TS;
    const int base_i = min(max(i0 - 3, 0), Hh - Kk);
    const int base_j = min(max(j0 - 3, 0), Ww - Kk);

    for (int e = tid; e < NIDX * 32; e += 128) {
        int row = e >> 5, c4 = e & 31;
        int gi = min(base_i + row / NROWS, Hh - 1);
        int gj = min(base_j + row % NROWS, Ww - 1);
        const float4* src = (const float4*)(g_qkv + (((long)(b * Hh + gi) * Ww) + gj) * QKVN);
        int c = c4 * 4;
        if (c < 64) {                       // k (cols 128..255 of qkv)
            float4 v = src[(128 + h0 * 32 + c) >> 2];
            int hl = c >> 5, d = c & 31;
            *(float4*)&sK[(hl * NIDX + row) * STRD + d] = v;
        } else {                            // v (cols 256..383)
            int cc = c - 64;
            float4 v = src[(256 + h0 * 32 + cc) >> 2];
            int hl = cc >> 5, d = cc & 31;
            *(float4*)&sV[(hl * NIDX + row) * STRD + d] = v;
        }
    }
    __syncthreads();

    const int px = tid & 63, hl = tid >> 6;
    const int h = h0 + hl;
    const int i = i0 + (px >> 3), j = j0 + (px & 7);
    const int si = min(max(i - 3, 0), Hh - Kk);
    const int sj = min(max(j - 3, 0), Ww - Kk);
    const int li = si - base_i, lj = sj - base_j;
    const long np = (long)(b * Hh + i) * Ww + j;

    float4 q[8];
    const float4* qp = (const float4*)(g_qkv + np * QKVN + h * HDd);
    #pragma unroll
    for (int u = 0; u < 8; u++) q[u] = qp[u];

    const float* rp = rpb + h * 169 + (si - i + 6) * 13 + (sj - j + 6);
    const float* kbase = sK + hl * NIDX * STRD;
    const float* vbase = sV + hl * NIDX * STRD;

    float sc[49];
    #pragma unroll
    for (int a = 0; a < 7; a++) {
        #pragma unroll
        for (int bb = 0; bb < 7; bb++) {
            const float4* kk = (const float4*)(kbase + ((li + a) * NROWS + lj + bb) * STRD);
            float s = 0.f;
            #pragma unroll
            for (int u = 0; u < 8; u++) {
                float4 kv4 = kk[u];
                s += q[u].x * kv4.x; s += q[u].y * kv4.y;
                s += q[u].z * kv4.z; s += q[u].w * kv4.w;
            }
            sc[a * 7 + bb] = s + __ldg(&rp[a * 13 + bb]);
        }
    }

    float mx = sc[0];
    #pragma unroll
    for (int n = 1; n < 49; n++) mx = fmaxf(mx, sc[n]);
    float sum = 0.f;
    #pragma unroll
    for (int n = 0; n < 49; n++) { sc[n] = expf(sc[n] - mx); sum += sc[n]; }
    const float inv = 1.0f / sum;

    float4 acc[8];
    #pragma unroll
    for (int u = 0; u < 8; u++) acc[u] = make_float4(0.f, 0.f, 0.f, 0.f);
    #pragma unroll
    for (int a = 0; a < 7; a++) {
        #pragma unroll
        for (int bb = 0; bb < 7; bb++) {
            float p = sc[a * 7 + bb] * inv;
            const float4* vv = (const float4*)(vbase + ((li + a) * NROWS + lj + bb) * STRD);
            #pragma unroll
            for (int u = 0; u < 8; u++) {
                float4 v4 = vv[u];
                acc[u].x += p * v4.x; acc[u].y += p * v4.y;
                acc[u].z += p * v4.z; acc[u].w += p * v4.w;
            }
        }
    }
    __nv_bfloat162* op = (__nv_bfloat162*)(g_att + np * Cc + h * HDd);
    #pragma unroll
    for (int u = 0; u < 8; u++) {
        op[u*2]   = __floats2bfloat162_rn(acc[u].x, acc[u].y);
        op[u*2+1] = __floats2bfloat162_rn(acc[u].z, acc[u].w);
    }
}

// ---------------- launch -----------------------------------------------------
extern "C" void kernel_launch(void* const* d_in, const int* in_sizes, int n_in,
                              void* d_out, int out_size)
{
    const float* query     = (const float*)d_in[0];
    const float* key_value = (const float*)d_in[1];
    const float* g1 = (const float*)d_in[2],  *b1 = (const float*)d_in[3];
    const float* g2 = (const float*)d_in[4],  *b2 = (const float*)d_in[5];
    const float* g3 = (const float*)d_in[6],  *b3 = (const float*)d_in[7];
    const float* Wq = (const float*)d_in[8],  *bq = (const float*)d_in[9];
    const float* Wkv= (const float*)d_in[10], *bkv= (const float*)d_in[11];
    const float* Wp = (const float*)d_in[12], *bp = (const float*)d_in[13];
    const float* rpb= (const float*)d_in[14];
    const float* W1 = (const float*)d_in[15], *bm1= (const float*)d_in[16];
    const float* W2 = (const float*)d_in[17], *bm2= (const float*)d_in[18];
    float* out = (float*)d_out;

    __nv_bfloat16 *qn, *kvn, *att, *xn, *mid, *wqkv, *wp, *w1, *w2;
    float *qkv, *x, *bqkv;
    cudaGetSymbolAddress((void**)&qn,   g_qn);
    cudaGetSymbolAddress((void**)&kvn,  g_kvn);
    cudaGetSymbolAddress((void**)&qkv,  g_qkv);
    cudaGetSymbolAddress((void**)&att,  g_att);
    cudaGetSymbolAddress((void**)&x,    g_x);
    cudaGetSymbolAddress((void**)&xn,   g_xn);
    cudaGetSymbolAddress((void**)&mid,  g_mid);
    cudaGetSymbolAddress((void**)&wqkv, g_wqkv);
    cudaGetSymbolAddress((void**)&wp,   g_wp);
    cudaGetSymbolAddress((void**)&w1,   g_w1);
    cudaGetSymbolAddress((void**)&w2,   g_w2);
    cudaGetSymbolAddress((void**)&bqkv, g_bqkv);

    cudaFuncSetAttribute(natt_kernel, cudaFuncAttributeMaxDynamicSharedMemorySize, NATT_SMEM);

    // 1: fused coalesced weight/bias packing
    pack_all<<<194, 256>>>(Wq, Wkv, Wp, W1, W2, bq, bkv);

    // 2: both input LayerNorms in one launch
    ln2_kernel<<<dim3(Ntok / 8, 2), 256>>>(query, g1, b1, qn,
                                           key_value, g2, b2, kvn);

    // 3: fused QKV GEMM: bn==0 -> A=qn (q cols), bn>0 -> A=kvn (k,v cols)
    gemm_mma<0><<<dim3(3, Ntok/128), 256>>>(qn, kvn, wqkv, bqkv, nullptr, qkv,
                                            Ntok, 128, QKVN);

    // 4: neighborhood attention -> att (bf16)
    natt_kernel<<<dim3(Ww/TS, Hh/TS, Bsz*2), 128, NATT_SMEM>>>(rpb);

    // 5: x = key_value + att @ Wp + bp   (f32)
    gemm_mma<1><<<dim3(1, Ntok/128), 256>>>(att, att, wp, bp, key_value, x,
                                            Ntok, 128, 128);

    // 6: xn = LN(x) -> bf16
    ln2_kernel<<<dim3(Ntok / 8, 1), 256>>>(x, g3, b3, xn, x, g3, b3, xn);

    // 7: mid = gelu(xn @ W1 + bm1) -> bf16
    gemm_mma<2><<<dim3(4, Ntok/128), 256>>>(xn, xn, w1, bm1, nullptr, mid,
                                            Ntok, 128, MLPD);

    // 8: out = x + mid @ W2 + bm2  (f32)
    gemm_mma<1><<<dim3(1, Ntok/128), 256>>>(mid, mid, w2, bm2, x, out,
                                            Ntok, MLPD, 128);
}